// round 6
// baseline (speedup 1.0000x reference)
#include <cuda_runtime.h>
#include <cuda_bf16.h>

#define NUM_HIST 4
#define MAX_T    16      // timesteps after history slice (fixed shape: 20-4)
#define CAP      128     // max candidates staged in smem; fallback to global path above this
#define CAPP     (CAP + 1)  // padded stride -> conflict-free LDS

__device__ __forceinline__ float reluf(float x) { return x > 0.0f ? x : 0.0f; }

__device__ __forceinline__ float overlap(float lx, float ly,
                                         float f, float r, float l, float rt) {
    float a = fminf(reluf(f - lx), reluf(r + lx));
    float b = fminf(reluf(l - ly), reluf(rt + ly));
    return fminf(a, b);
}

// Pair test: returns true if max(A,B) > 0 for (ego corners vs agent box) and
// (agent corners vs ego box).
__device__ __forceinline__ bool pair_hit(
    float ex, float ey, float ce, float se,
    float ef, float er, float el, float ert,
    const float* ecx, const float* ecy,
    float nx, float ny, float cn, float sn,
    float nf, float nr, float nl, float nrt)
{
    float A = 0.0f;
#pragma unroll
    for (int c = 0; c < 4; c++) {
        float dx = ecx[c] - nx;
        float dy = ecy[c] - ny;
        float alx =  cn * dx + sn * dy;
        float aly = -sn * dx + cn * dy;
        A = fmaxf(A, overlap(alx, aly, nf, nr, nl, nrt));
    }
    float B = 0.0f;
    {
        const float lx[4] = { nf,  nf, -nr, -nr };
        const float ly[4] = { nl, -nrt, -nrt, nl };
#pragma unroll
        for (int c = 0; c < 4; c++) {
            float cxg = nx + cn * lx[c] - sn * ly[c];
            float cyg = ny + sn * lx[c] + cn * ly[c];
            float dx = cxg - ex;
            float dy = cyg - ey;
            float blx =  ce * dx + se * dy;
            float bly = -se * dx + ce * dy;
            B = fmaxf(B, overlap(blx, bly, ef, er, el, ert));
        }
    }
    return fmaxf(A, B) > 0.0f;
}

// One block per ego e, one warp per timestep t.
// 1) parallel probe of sorted batch[] -> contiguous candidate range [lo, hi)
// 2) coalesced staging of candidate yaw/pos/msk/box into smem, transposed to
//    [t][agent] (padded stride 129 -> conflict-free LDS)
// 3) per-warp pair loop over candidates entirely from smem
// 4) ballot -> done[e*T+t]; thread 0 folds reward[e]. Single launch.
__global__ void fused_kernel(const float* __restrict__ pos,          // (N, T_TOT, 2)
                             const float* __restrict__ yaw,          // (N, T_TOT)
                             const unsigned int* __restrict__ msk,   // (N, T_TOT) bool as 32-bit
                             const float* __restrict__ box,          // (N, 4)
                             const int* __restrict__ batch,          // (N,) sorted
                             const int* __restrict__ ego,            // (Ne,)
                             float* __restrict__ out,                // [done.T | reward]
                             int N, int T_TOT, int T, int Ne)
{
    const int e    = blockIdx.x;
    const int t    = threadIdx.x >> 5;
    const int lane = threadIdx.x & 31;

    __shared__ int   s_lo, s_hi;
    __shared__ float sdone[32];
    __shared__ float s_yaw[MAX_T * CAPP];
    __shared__ float s_px [MAX_T * CAPP];
    __shared__ float s_py [MAX_T * CAPP];
    __shared__ unsigned int s_msk[MAX_T * CAPP];
    __shared__ float s_bf[CAP], s_br[CAP], s_bl[CAP], s_brt[CAP];

    const int ei = ego[e];
    const int eb = batch[ei];

    if (threadIdx.x == 0) { s_lo = N; s_hi = 0; }
    __syncthreads();

    // Parallel range-find over sorted batch[] (coalesced, one round-trip).
    for (int n = threadIdx.x; n < N; n += blockDim.x) {
        if (batch[n] == eb) {
            atomicMin(&s_lo, n);
            atomicMax(&s_hi, n + 1);
        }
    }
    __syncthreads();
    const int lo  = s_lo, hi = s_hi;
    const int cnt = hi - lo;

    // Per-warp ego state (independent of staging; issue early).
    const int tt = t + NUM_HIST;
    float eyaw = 0.f, ex = 0.f, ey = 0.f, ef = 0.f, er = 0.f, el = 0.f, ert = 0.f;
    unsigned int emv = 0u;
    if (t < T) {
        eyaw = yaw[ei * T_TOT + tt];
        float2 ep = ((const float2*)pos)[ei * T_TOT + tt];
        ex = ep.x; ey = ep.y;
        emv = msk[ei * T_TOT + tt];
        float4 ebx = ((const float4*)box)[ei];
        ef = ebx.x; er = ebx.y; el = ebx.z; ert = ebx.w;
    }
    float ce, se;
    sincosf(eyaw, &se, &ce);
    float ecx[4], ecy[4];
    {
        const float lx[4] = { ef,  ef, -er, -er };
        const float ly[4] = { el, -ert, -ert, el };
#pragma unroll
        for (int c = 0; c < 4; c++) {
            ecx[c] = ex + ce * lx[c] - se * ly[c];
            ecy[c] = ey + se * lx[c] + ce * ly[c];
        }
    }

    int any_edge = 0;
    int any_hit  = 0;

    if (cnt <= CAP && T <= MAX_T) {
        // ---- Staged path: coalesced gather into smem ----
        for (int idx = threadIdx.x; idx < cnt * T; idx += blockDim.x) {
            int j  = idx / T;
            int tq = idx - j * T;
            int g  = (lo + j) * T_TOT + NUM_HIST + tq;
            s_yaw[tq * CAPP + j] = yaw[g];
            float2 p = ((const float2*)pos)[g];
            s_px[tq * CAPP + j] = p.x;
            s_py[tq * CAPP + j] = p.y;
            s_msk[tq * CAPP + j] = msk[g];
        }
        for (int j = threadIdx.x; j < cnt; j += blockDim.x) {
            float4 b = ((const float4*)box)[lo + j];
            s_bf[j] = b.x; s_br[j] = b.y; s_bl[j] = b.z; s_brt[j] = b.w;
        }
        __syncthreads();

        if (t < T && emv != 0u) {
            const int row = t * CAPP;
            for (int j = lane; j < cnt; j += 32) {
                const bool valid = (s_msk[row + j] != 0u) && (lo + j != ei);
                any_edge |= valid ? 1 : 0;

                const float nyaw = s_yaw[row + j];
                const float nx   = s_px[row + j];
                const float ny   = s_py[row + j];
                float cn, sn;
                sincosf(nyaw, &sn, &cn);

                bool hit = pair_hit(ex, ey, ce, se, ef, er, el, ert, ecx, ecy,
                                    nx, ny, cn, sn,
                                    s_bf[j], s_br[j], s_bl[j], s_brt[j]);
                any_hit |= (valid && hit) ? 1 : 0;
            }
        }
    } else {
        // ---- Fallback: global-load path (range larger than CAP) ----
        if (t < T && emv != 0u) {
            for (int n = lo + lane; n < hi; n += 32) {
                const unsigned int nmv = msk[n * T_TOT + tt];
                const float nyaw = yaw[n * T_TOT + tt];
                float2 p = ((const float2*)pos)[n * T_TOT + tt];
                float4 b = ((const float4*)box)[n];

                const bool valid = (nmv != 0u) && (n != ei);
                any_edge |= valid ? 1 : 0;

                float cn, sn;
                sincosf(nyaw, &sn, &cn);
                bool hit = pair_hit(ex, ey, ce, se, ef, er, el, ert, ecx, ecy,
                                    p.x, p.y, cn, sn, b.x, b.y, b.z, b.w);
                any_hit |= (valid && hit) ? 1 : 0;
            }
        }
    }

    if (t < T) {
        const unsigned be = __ballot_sync(0xffffffffu, any_edge);
        const unsigned bh = __ballot_sync(0xffffffffu, any_hit);
        const float d = (be != 0u && bh != 0u) ? 1.0f : 0.0f;
        if (lane == 0) {
            out[e * T + t] = d;   // done.T layout: [e, t]
            sdone[t] = d;
        }
    }
    __syncthreads();

    if (threadIdx.x == 0) {
        float r = 1.0f;
        for (int k = 0; k < T; k++) {
            if (sdone[k] != 0.0f) r = 0.0f;
        }
        out[Ne * T + e] = r;
    }
}

extern "C" void kernel_launch(void* const* d_in, const int* in_sizes, int n_in,
                              void* d_out, int out_size)
{
    const float*        pos   = (const float*)d_in[0];         // (N, T_TOT, 2)
    const float*        yaw   = (const float*)d_in[1];         // (N, T_TOT)
    const unsigned int* msk   = (const unsigned int*)d_in[2];  // (N, T_TOT) bool as 32-bit
    const float*        box   = (const float*)d_in[3];         // (N, 4)
    const int*          batch = (const int*)d_in[4];           // (N,)
    const int*          ego   = (const int*)d_in[5];           // (Ne,)
    float*              out   = (float*)d_out;

    const int N     = in_sizes[4];
    const int T_TOT = in_sizes[1] / N;
    const int T     = T_TOT - NUM_HIST;   // 16
    const int Ne    = in_sizes[5];        // 64

    fused_kernel<<<Ne, 32 * T>>>(pos, yaw, msk, box, batch, ego, out,
                                 N, T_TOT, T, Ne);
}

// round 7
// speedup vs baseline: 1.2043x; 1.2043x over previous
#include <cuda_runtime.h>
#include <cuda_bf16.h>

#define NUM_HIST 4

__device__ __forceinline__ float reluf(float x) { return x > 0.0f ? x : 0.0f; }

// overlap(): min of relu'd signed distances to box faces (LONG_T = LAT_T = 0)
__device__ __forceinline__ float overlap(float lx, float ly,
                                         float f, float r, float l, float rt) {
    float a = fminf(reluf(f - lx), reluf(r + lx));
    float b = fminf(reluf(l - ly), reluf(rt + ly));
    return fminf(a, b);
}

// One block per ego e, one warp per timestep t (blockDim = 32*T).
// 1) parallel strided probe of sorted batch[] -> contiguous range [lo, hi)
// 2) each warp scans the range with vectorized (float2/float4) loads,
//    ballots "any edge" / "any hit", lane 0 writes done[e*T+t]
// 3) block-wide __syncthreads_or folds reward[e] with no extra smem/loop.
__global__ void fused_kernel(const float* __restrict__ pos,          // (N, T_TOT, 2)
                             const float* __restrict__ yaw,          // (N, T_TOT)
                             const unsigned int* __restrict__ msk,   // (N, T_TOT) bool as 32-bit
                             const float* __restrict__ box,          // (N, 4)
                             const int* __restrict__ batch,          // (N,) sorted
                             const int* __restrict__ ego,            // (Ne,)
                             float* __restrict__ out,                // [done.T | reward]
                             int N, int T_TOT, int T, int Ne)
{
    const int e    = blockIdx.x;
    const int t    = threadIdx.x >> 5;   // warp id == timestep (always < T)
    const int lane = threadIdx.x & 31;

    __shared__ int s_lo, s_hi;

    const int ei = ego[e];
    const int eb = batch[ei];

    if (threadIdx.x == 0) { s_lo = N; s_hi = 0; }
    __syncthreads();

    // Parallel range-find over sorted batch[] (coalesced, independent probes).
    for (int n = threadIdx.x; n < N; n += blockDim.x) {
        if (batch[n] == eb) {
            atomicMin(&s_lo, n);
            atomicMax(&s_hi, n + 1);
        }
    }
    __syncthreads();
    const int lo = s_lo, hi = s_hi;

    // Per-warp ego state (vector loads).
    const int tt = t + NUM_HIST;
    const float eyaw = yaw[ei * T_TOT + tt];
    const float2 ep  = ((const float2*)pos)[ei * T_TOT + tt];
    const unsigned int emv = msk[ei * T_TOT + tt];
    const float4 ebx = ((const float4*)box)[ei];
    const float ex = ep.x, ey = ep.y;
    const float ef = ebx.x, er = ebx.y, el = ebx.z, ert = ebx.w;

    float ce, se;
    sincosf(eyaw, &se, &ce);

    // ego corner positions (global frame)
    float ecx[4], ecy[4];
    {
        const float lx[4] = { ef,  ef, -er, -er };
        const float ly[4] = { el, -ert, -ert, el };
#pragma unroll
        for (int c = 0; c < 4; c++) {
            ecx[c] = ex + ce * lx[c] - se * ly[c];
            ecy[c] = ey + se * lx[c] + ce * ly[c];
        }
    }

    int any_edge = 0;
    int any_hit  = 0;

    if (emv != 0u) {
        for (int n = lo + lane; n < hi; n += 32) {
            // 4 independent vector loads per candidate.
            const unsigned int nmv = msk[n * T_TOT + tt];
            const float nyaw = yaw[n * T_TOT + tt];
            const float2 p   = ((const float2*)pos)[n * T_TOT + tt];
            const float4 b   = ((const float4*)box)[n];

            const bool valid = (nmv != 0u) && (n != ei);
            any_edge |= valid ? 1 : 0;

            float cn, sn;
            sincosf(nyaw, &sn, &cn);
            const float nx = p.x, ny = p.y;
            const float nf = b.x, nr = b.y, nl = b.z, nrt = b.w;

            // A: ego corners in agent-n frame, overlap vs agent box
            float A = 0.0f;
#pragma unroll
            for (int c = 0; c < 4; c++) {
                float dx = ecx[c] - nx;
                float dy = ecy[c] - ny;
                float alx =  cn * dx + sn * dy;
                float aly = -sn * dx + cn * dy;
                A = fmaxf(A, overlap(alx, aly, nf, nr, nl, nrt));
            }

            // B: agent-n corners in ego frame, overlap vs ego box
            float B = 0.0f;
            {
                const float lx[4] = { nf,  nf, -nr, -nr };
                const float ly[4] = { nl, -nrt, -nrt, nl };
#pragma unroll
                for (int c = 0; c < 4; c++) {
                    float cxg = nx + cn * lx[c] - sn * ly[c];
                    float cyg = ny + sn * lx[c] + cn * ly[c];
                    float dx = cxg - ex;
                    float dy = cyg - ey;
                    float blx =  ce * dx + se * dy;
                    float bly = -se * dx + ce * dy;
                    B = fmaxf(B, overlap(blx, bly, ef, er, el, ert));
                }
            }

            any_hit |= (valid && fmaxf(A, B) > 0.0f) ? 1 : 0;
        }
    }

    const unsigned be = __ballot_sync(0xffffffffu, any_edge);
    const unsigned bh = __ballot_sync(0xffffffffu, any_hit);
    const int done_t = (be != 0u && bh != 0u) ? 1 : 0;

    if (lane == 0) {
        out[e * T + t] = done_t ? 1.0f : 0.0f;   // done.T layout: [e, t]
    }

    // Block-wide OR over all timesteps -> reward in one barrier.
    const int any_done = __syncthreads_or(done_t);
    if (threadIdx.x == 0) {
        out[Ne * T + e] = any_done ? 0.0f : 1.0f;
    }
}

extern "C" void kernel_launch(void* const* d_in, const int* in_sizes, int n_in,
                              void* d_out, int out_size)
{
    const float*        pos   = (const float*)d_in[0];         // (N, T_TOT, 2)
    const float*        yaw   = (const float*)d_in[1];         // (N, T_TOT)
    const unsigned int* msk   = (const unsigned int*)d_in[2];  // (N, T_TOT) bool as 32-bit
    const float*        box   = (const float*)d_in[3];         // (N, 4)
    const int*          batch = (const int*)d_in[4];           // (N,)
    const int*          ego   = (const int*)d_in[5];           // (Ne,)
    float*              out   = (float*)d_out;

    const int N     = in_sizes[4];
    const int T_TOT = in_sizes[1] / N;
    const int T     = T_TOT - NUM_HIST;   // 16
    const int Ne    = in_sizes[5];        // 64

    fused_kernel<<<Ne, 32 * T>>>(pos, yaw, msk, box, batch, ego, out,
                                 N, T_TOT, T, Ne);
}